// round 12
// baseline (speedup 1.0000x reference)
#include <cuda_runtime.h>

// ---------------------------------------------------------------------------
// SSIM (16,3,512,512) fp32, 11x11 Gaussian (sigma=1.5), zero pad, global mean.
// Separable conv; warp-private SMEM halo segments; static mod-11 f32x2 ring.
// cp.async depth-3 pipeline over 8 rotating buffers.
// R12: TRANS stage deleted — Hadamard commuted past the h-conv.
//   h-conv runs on raw (x|y) pairs: packed linear conv, packed square conv,
//   scalar cross (xy) conv; then once per row:
//     P=hx+hy, Q=hx-hy, SS=hxx+hyy+2hxy, DD=hxx+hyy-2hxy.
//   Ring/extraction identical to R11. Saves ~6 smem wavefronts/warp-row
//   (the measured L1 wall) for ~+20 cheap ALU/FMA slots.
// ---------------------------------------------------------------------------

#define IMW     512
#define IMH     512
#define NT      512                 // one thread per column
#define TH      171                 // output rows per band (3 bands cover 512)
#define NBANDS  3
#define NPLANES 48                  // 16 * 3
#define NBLOCKS (NPLANES * NBANDS)  // 144 CTAs -> single wave
#define SSIM_C1 0.0001f
#define SSIM_C2 0.0009f

typedef unsigned long long ull;

__device__ float        g_partials[NBLOCKS];
__device__ unsigned int g_count;    // zero-init; reset by last block each run

#define CPA4(daddr, sptr) \
    asm volatile("cp.async.ca.shared.global [%0], [%1], 4;" \
                 :: "r"(daddr), "l"(sptr))
// tail column: dst slot +256 B (32 slots * 8B), src +128 B (32 floats)
#define CPA4T(daddr, sptr) \
    asm volatile("cp.async.ca.shared.global [%0+256], [%1+128], 4;" \
                 :: "r"(daddr), "l"(sptr))
#define CPA_COMMIT() asm volatile("cp.async.commit_group;" ::: "memory")
#define CPA_WAIT2()  asm volatile("cp.async.wait_group 2;"  ::: "memory")

#define LDS64(d, a) \
    asm volatile("ld.shared.b64 %0, [%1];" : "=l"(d) : "r"(a))
#define ADD2(d, a, b) \
    asm("add.rn.f32x2 %0, %1, %2;" : "=l"(d) : "l"(a), "l"(b))
#define MUL2(d, a, b) \
    asm("mul.rn.f32x2 %0, %1, %2;" : "=l"(d) : "l"(a), "l"(b))
#define FMA2ACC(acc, a, b) \
    asm("fma.rn.f32x2 %0, %1, %2, %0;" : "+l"(acc) : "l"(a), "l"(b))
#define UNPACK2(lo, hi, s) \
    asm("mov.b64 {%0, %1}, %2;" : "=f"(lo), "=f"(hi) : "l"(s))
#define PACK2(d, lo, hi) \
    asm("mov.b64 %0, {%1, %2};" : "=l"(d) : "f"(lo), "f"(hi))

// h-conv + Hadamard fold + ring + extraction for row ir_ at buffer base rb_.
// P must be a compile-time constant == ir_ mod 11.
#define ROWCOMP(P, ir_, rb_) do {                                             \
    ull v[11];                                                                \
    _Pragma("unroll")                                                         \
    for (int k = 0; k < 11; ++k) LDS64(v[k], (rb_) + 8u * k);                 \
    ull hl, hs, t5;                 /* (hx|hy), (hxx|hyy) */                  \
    float hxy;                                                                \
    {                                                                         \
        MUL2(hl, v[5], W2[5]);                                                \
        MUL2(t5, v[5], v[5]);                                                 \
        MUL2(hs, t5, W2[5]);                                                  \
        float cx, cy; UNPACK2(cx, cy, v[5]);                                  \
        hxy = W[5] * (cx * cy);                                               \
    }                                                                         \
    _Pragma("unroll")                                                         \
    for (int k = 0; k < 5; ++k) {   /* symmetric pairs (k, 10-k) */           \
        ull ab, sq;                                                           \
        ADD2(ab, v[k], v[10 - k]);                                            \
        FMA2ACC(hl, ab, W2[k]);                                               \
        MUL2(sq, v[k], v[k]);                                                 \
        FMA2ACC(sq, v[10 - k], v[10 - k]);                                    \
        FMA2ACC(hs, sq, W2[k]);                                               \
        float xa, ya, xb, yb;                                                 \
        UNPACK2(xa, ya, v[k]);                                                \
        UNPACK2(xb, yb, v[10 - k]);                                           \
        float m = xa * ya;                                                    \
        m = fmaf(xb, yb, m);                                                  \
        hxy = fmaf(W[k], m, hxy);                                             \
    }                                                                         \
    /* Hadamard fold (once per row) */                                        \
    ull hPQ, hSD;                                                             \
    {                                                                         \
        float hx, hy; UNPACK2(hx, hy, hl);                                    \
        PACK2(hPQ, hx + hy, hx - hy);                                         \
        float hxx, hyy; UNPACK2(hxx, hyy, hs);                                \
        const float tt = hxx + hyy;                                           \
        PACK2(hSD, fmaf(2.f, hxy, tt), fmaf(-2.f, hxy, tt));                  \
    }                                                                         \
    _Pragma("unroll")                                                         \
    for (int s = 0; s < 11; ++s) {                                            \
        const int d = ((P) - s + 11) % 11;      /* compile-time */            \
        if (s == (P)) {     /* tap d==0: new output starts -> overwrite */    \
            MUL2(APQ[s], hPQ, W2[0]);                                         \
            MUL2(ASD[s], hSD, W2[0]);                                         \
        } else {                                                              \
            FMA2ACC(APQ[s], hPQ, W2[d]);                                      \
            FMA2ACC(ASD[s], hSD, W2[d]);                                      \
        }                                                                     \
    }                                                                         \
    const int e_ = ((P) + 1) % 11;              /* compile-time */            \
    if ((ir_) >= 10) {          /* output row m = ir-10 is real */            \
        float p, q, sv, dv;                                                   \
        UNPACK2(p, q, APQ[e_]);                                               \
        UNPACK2(sv, dv, ASD[e_]);                                             \
        const float a2 = p * p;                                               \
        const float b2 = q * q;                                               \
        const float U  = a2 + b2;                                             \
        const float V  = a2 - b2;                                             \
        const float M  = sv + dv;                                             \
        const float N2 = sv - dv;                                             \
        const float t1 = 0.5f * V + SSIM_C1;                                  \
        const float t2 = 0.5f * (N2 - V) + SSIM_C2;                           \
        const float t3 = 0.5f * U + SSIM_C1;                                  \
        const float t4 = 0.5f * (M - U) + SSIM_C2;                            \
        ssum += __fdividef(t1 * t2, t3 * t4);                                 \
    }                                                                         \
} while (0)

// Guard-free phase (full blocks: ir < 176, fill row ir+3 <= 178 < nrows).
#define PHASEF(P, IRV) do {                                                   \
    const int irf_ = (IRV);                                                   \
    CPA_WAIT2();                                                              \
    const unsigned rbf_ = sbu + (unsigned)(irf_ & 7) * BSTRIDE;               \
    FILLF(irf_ + 3);                                                          \
    CPA_COMMIT();                                                             \
    __syncwarp();                                                             \
    ROWCOMP(P, irf_, rbf_);                                                   \
} while (0)

// Guarded tail phase (rows 176..nrows-1).
#define PHASET(P, IRV) do {                                                   \
    const int irt_ = (IRV);                                                   \
    if (irt_ < nrows) {                                                       \
        CPA_WAIT2();                                                          \
        const unsigned rbt_ = sbu + (unsigned)(irt_ & 7) * BSTRIDE;           \
        if (irt_ + 3 < nrows) FILLF(irt_ + 3);                                \
        CPA_COMMIT();                                                         \
        __syncwarp();                                                         \
        ROWCOMP(P, irt_, rbt_);                                               \
    }                                                                         \
} while (0)

__global__ void __launch_bounds__(NT, 1)
ssim_main(const float* __restrict__ img1, const float* __restrict__ img2,
          float* __restrict__ out)
{
    // Normalized 1D Gaussian, sigma=1.5, 11 taps
    const float W[11] = {
        0.00102838f, 0.00759874f, 0.03600077f, 0.10936069f, 0.21300553f,
        0.26601180f,
        0.21300553f, 0.10936069f, 0.03600077f, 0.00759874f, 0.00102838f
    };
    // Duplicated 64-bit weight pairs (w|w) for f32x2 ops
    ull W2[11];
#pragma unroll
    for (int k = 0; k < 11; ++k) {
        const unsigned u = __float_as_uint(W[k]);
        W2[k] = ((ull)u << 32) | (ull)u;
    }

    const int band  = blockIdx.x;           // 0..2
    const int plane = blockIdx.y;           // 0..47
    const int t     = threadIdx.x;          // column 0..511
    const int l     = t & 31;               // lane
    const int w     = t >> 5;               // warp
    const int r0    = band * TH;
    const int rows  = (IMH - r0 < TH) ? (IMH - r0) : TH;   // 171/171/170
    const int nrows = rows + 10;            // 181/181/180
    const int pbase = plane * (IMW * IMH);

    // Warp-private 8-deep rotating halo segments, raw (img1, img2) pairs.
    // seg[buf][w][j], j in [0,42): pixel pair at image column 32*w - 5 + j.
    __shared__ float2 seg[8][16][44];

    // Static ring (packed): slot s <-> output rows m with m % 11 == s.
    ull APQ[11], ASD[11];
#pragma unroll
    for (int j = 0; j < 11; ++j) { APQ[j] = 0ULL; ASD[j] = 0ULL; }

    // Column mapping:
    //   slot j = l      <-> col t - 5   (valid iff t >= 5)
    //   slot j = 32 + l <-> col t + 27  (exists iff l < 10, valid iff < 512)
    const bool mainok = (t >= 5);
    const bool tailst = (l < 10);
    const bool tailok = tailst && (t + 27 < IMW);

    // Base pointers for this lane's main column (col t-5), row gr=0.
    const float* bp1 = img1 + pbase + (t - 5);
    const float* bp2 = img2 + pbase + (t - 5);

    // u32 shared address of this warp+lane's slot in buffer 0
    unsigned sbu;
    asm("{ .reg .u64 tt; cvta.to.shared.u64 tt, %1; cvt.u32.u64 %0, tt; }"
        : "=r"(sbu) : "l"(&seg[0][w][l]));
    const unsigned BSTRIDE = 16u * 44u * 8u;   // bytes per buffer (5632)

    auto FILLF = [&](int rn) {
        const int gr = r0 - 5 + rn;             // global row (zero pad if OOB)
        const unsigned d = sbu + (unsigned)(rn & 7) * BSTRIDE;
        if ((unsigned)gr < (unsigned)IMH) {
            const float* p1 = bp1 + gr * IMW;   // one IMAD.WIDE each
            const float* p2 = bp2 + gr * IMW;
            if (mainok) { CPA4(d, p1);       CPA4(d + 4u, p2); }
            if (tailok) { CPA4T(d, p1);      CPA4T(d + 4u, p2); }
        } else {
            const float z = 0.f;
            asm volatile("st.shared.v2.f32 [%0], {%1,%1};" :: "r"(d), "f"(z));
            if (tailst)
                asm volatile("st.shared.v2.f32 [%0+256], {%1,%1};"
                             :: "r"(d), "f"(z));
        }
    };

    // Pre-zero slots never written by cp.async (col-invalid); all 8 buffers.
#pragma unroll
    for (int b = 0; b < 8; ++b) {
        if (!mainok)           seg[b][w][l]      = make_float2(0.f, 0.f);
        if (tailst && !tailok) seg[b][w][32 + l] = make_float2(0.f, 0.f);
    }

    // Prologue: rows 0,1,2 in flight as three groups.
    FILLF(0); CPA_COMMIT();
    FILLF(1); CPA_COMMIT();
    FILLF(2); CPA_COMMIT();
    __syncwarp();

    float ssum = 0.f;

    // 16 guard-free blocks: rows 0..175 (fill rows reach 178 <= nrows-2).
#pragma unroll 1
    for (int base = 0; base < 176; base += 11) {
#pragma unroll
        for (int q = 0; q < 11; ++q) {
            PHASEF(q, base + q);
        }
    }
    // Guarded tail: rows 176..nrows-1 (176 % 11 == 0 -> P == q).
    {
#pragma unroll
        for (int q = 0; q < 11; ++q) {
            PHASET(q, 176 + q);
        }
    }

    // ---- deterministic block reduction ----
    __syncthreads();
#pragma unroll
    for (int off = 16; off; off >>= 1)
        ssum += __shfl_xor_sync(0xffffffffu, ssum, off);

    __shared__ float wsum[16];
    __shared__ bool  islast;
    if (l == 0) wsum[w] = ssum;
    __syncthreads();
    if (t == 0) {
        float v = 0.f;
#pragma unroll
        for (int i = 0; i < 16; ++i) v += wsum[i];
        g_partials[plane * NBANDS + band] = v;
        __threadfence();
        const unsigned n = atomicAdd(&g_count, 1u);
        islast = (n == (unsigned)(NBLOCKS - 1));
    }
    __syncthreads();

    // ---- last CTA: fixed-order (deterministic) final reduction ----
    if (islast) {
        __threadfence();
        float v = (t < NBLOCKS) ? g_partials[t] : 0.f;
#pragma unroll
        for (int off = 16; off; off >>= 1)
            v += __shfl_xor_sync(0xffffffffu, v, off);
        if (l == 0) wsum[w] = v;
        __syncthreads();
        if (t == 0) {
            float s = 0.f;
#pragma unroll
            for (int i = 0; i < 16; ++i) s += wsum[i];
            out[0] = s * (1.0f / 12582912.0f);  // / (16*3*512*512)
            g_count = 0u;                        // reset for next graph replay
        }
    }
}

extern "C" void kernel_launch(void* const* d_in, const int* in_sizes, int n_in,
                              void* d_out, int out_size)
{
    const float* img1 = (const float*)d_in[0];
    const float* img2 = (const float*)d_in[1];
    (void)in_sizes; (void)n_in; (void)out_size;

    dim3 grid(NBANDS, NPLANES);
    ssim_main<<<grid, NT>>>(img1, img2, (float*)d_out);
}